// round 8
// baseline (speedup 1.0000x reference)
#include <cuda_runtime.h>
#include <cstdint>

// out = x + exp(0.5*(relu(x@W1+b1)@W2 + b2)) * eps
// x,eps,out [B,256] f32; W1 [256,64]; b1[64]; W2 [64,256]; b2[256]
// Persistent mma.sync tf32 kernel, 512 threads, fragment-major smem layouts
// (LDS.128 for all W/H fragments) + epilogue load/MMA overlap.

#define SDIM 256
#define TMR  128
#define NTHREADS 512

// smem float-index offsets
#define W1F 0          // W1 tf32 fragment-major [k=256][64]   (64 KB)
#define W2F 16384      // W2 tf32 fragment-major [k=64][256]   (64 KB)
#define XS0 32768      // X chunk slot0: 128 rows x 64 k       (32 KB)
#define XS1 40960      // slot1                                (32 KB)
#define HS  49152      // H tf32 reader-order: 8 wh x 1024 fl  (32 KB)
#define B1S 57344      // 64 f32
#define B2S 57408      // 256 f32
#define SMEM_FLOATS 57664
#define SMEM_BYTES  (SMEM_FLOATS * 4)   // 230656

__device__ __forceinline__ uint32_t to_tf32(float f) {
    uint32_t r; asm("cvt.rna.tf32.f32 %0, %1;" : "=r"(r) : "f"(f)); return r;
}
__device__ __forceinline__ float ex2f(float f) {
    float r; asm("ex2.approx.f32 %0, %1;" : "=f"(r) : "f"(f)); return r;
}
__device__ __forceinline__ void mma8(float* c,
    uint32_t a0, uint32_t a1, uint32_t a2, uint32_t a3, uint32_t b0, uint32_t b1) {
    asm volatile(
        "mma.sync.aligned.m16n8k8.row.col.f32.tf32.tf32.f32 "
        "{%0,%1,%2,%3},{%4,%5,%6,%7},{%8,%9},{%0,%1,%2,%3};"
        : "+f"(c[0]), "+f"(c[1]), "+f"(c[2]), "+f"(c[3])
        : "r"(a0), "r"(a1), "r"(a2), "r"(a3), "r"(b0), "r"(b1));
}
static __device__ __forceinline__ uint32_t smem_u32(const void* p) {
    uint32_t a;
    asm("{ .reg .u64 t; cvta.to.shared.u64 t, %1; cvt.u32.u64 %0, t; }" : "=r"(a) : "l"(p));
    return a;
}
#define CPA16(s, g)  asm volatile("cp.async.cg.shared.global [%0], [%1], 16;" :: "r"(s), "l"(g))
#define CPCOMMIT()   asm volatile("cp.async.commit_group;" ::: "memory")
#define CPWAIT1()    asm volatile("cp.async.wait_group 1;" ::: "memory")

// fragment-major weight offset: element (k, n) of a [*, ld] matrix
// off = k*ld + (nt>>2)*32 + g*4 + (nt&3), g=n&7, nt=n>>3
__device__ __forceinline__ int wfrag_off(int k, int n, int ld) {
    int g = n & 7, nt = n >> 3;
    return k * ld + ((nt >> 2) << 5) + (g << 2) + (nt & 3);
}

// load one X chunk (128 rows x 64 floats) into a swizzled slot via cp.async
static __device__ __forceinline__ void load_chunk(
    const float* __restrict__ xT, int ck, float* slot) {
    const int tid = threadIdx.x;
    const float* gsrc = xT + ck * 64;
    #pragma unroll
    for (int j = 0; j < 4; j++) {
        int f = tid + NTHREADS * j;
        int m = f >> 4, c4 = f & 15;
        uint32_t dst = smem_u32(slot + m * 64 + 4 * (c4 ^ (m & 7)));
        CPA16(dst, gsrc + m * SDIM + 4 * c4);
    }
}

__global__ void __launch_bounds__(NTHREADS, 1) mvn_fm_kernel(
    const float* __restrict__ x, const float* __restrict__ eps,
    const float* __restrict__ W1, const float* __restrict__ b1,
    const float* __restrict__ W2, const float* __restrict__ b2,
    float* __restrict__ out, int numTiles)
{
    extern __shared__ float sm[];
    uint32_t* smu = reinterpret_cast<uint32_t*>(sm);

    const int tid  = threadIdx.x;
    const int w    = tid >> 5;
    const int wh   = w & 7;       // row group: rows 16*wh .. +15
    const int ns   = w >> 3;      // n-split half
    const int lane = tid & 31;
    const int g    = lane >> 2;
    const int t4   = lane & 3;

    // ---- stage weights (tf32, fragment-major) + biases ----
    #pragma unroll 4
    for (int j = 0; j < 32; j++) {
        int idx = tid + NTHREADS * j;
        int kk = idx >> 6, n = idx & 63;
        smu[W1F + wfrag_off(kk, n, 64)] = to_tf32(W1[idx]);
    }
    #pragma unroll 4
    for (int j = 0; j < 32; j++) {
        int idx = tid + NTHREADS * j;
        int kk = idx >> 8, n = idx & 255;
        smu[W2F + wfrag_off(kk, n, 256)] = to_tf32(W2[idx]);
    }
    if (tid < 64) sm[B1S + tid] = b1[tid];
    if (tid >= 64 && tid < 320) sm[B2S + tid - 64] = b2[tid - 64];
    __syncthreads();

    const int G = gridDim.x;
    const long long TS = (long long)TMR * SDIM;
    int t = blockIdx.x;

    load_chunk(x + t * TS, 0, sm + XS0); CPCOMMIT();
    load_chunk(x + t * TS, 1, sm + XS1); CPCOMMIT();

    const int arow = (16 * wh + g) * 64 + t4;       // X A-fragment base
    const int hwb  = HS + wh * 1024;                // this row-group's H region
    const int hrd  = hwb + g * 16 + t4 * 4;         // reader A base (per ks: +128)
    const int hwr  = hwb + g * 16 + (t4 & 1) * 8 + (t4 >> 1) * 2;  // writer base

    for (; t < numTiles; t += G) {
        const long long base = t * TS;
        const float* xT = x + base;

        // ======== GEMM1: this warp computes H cols 32*ns..+31 ========
        float acc1[4][4];
        #pragma unroll
        for (int nt = 0; nt < 4; nt++)
            acc1[nt][0] = acc1[nt][1] = acc1[nt][2] = acc1[nt][3] = 0.0f;

        #pragma unroll
        for (int c = 0; c < 4; c++) {
            CPWAIT1();
            __syncthreads();
            const float* xs = sm + ((c & 1) ? XS1 : XS0);

            #pragma unroll
            for (int ks = 0; ks < 8; ks++) {
                int a0i = arow + 4 * ((2 * ks) ^ g);
                uint32_t A0 = to_tf32(xs[a0i]);
                uint32_t A1 = to_tf32(xs[a0i + 512]);
                uint32_t A2 = to_tf32(xs[a0i ^ 4]);
                uint32_t A3 = to_tf32(xs[(a0i ^ 4) + 512]);
                int wr = (64 * c + 8 * ks + t4) * 64 + ns * 32 + g * 4;
                uint4 B0 = *reinterpret_cast<const uint4*>(&smu[W1F + wr]);
                uint4 B1 = *reinterpret_cast<const uint4*>(&smu[W1F + wr + 256]); // row +4
                mma8(acc1[0], A0, A1, A2, A3, B0.x, B1.x);
                mma8(acc1[1], A0, A1, A2, A3, B0.y, B1.y);
                mma8(acc1[2], A0, A1, A2, A3, B0.z, B1.z);
                mma8(acc1[3], A0, A1, A2, A3, B0.w, B1.w);
            }
            __syncthreads();

            int tn = t + G;
            if (c == 0)      { load_chunk(xT, 2, sm + XS0); }
            else if (c == 1) { load_chunk(xT, 3, sm + XS1); }
            else if (c == 2) { if (tn < numTiles) load_chunk(x + tn * TS, 0, sm + XS0); }
            else             { if (tn < numTiles) load_chunk(x + tn * TS, 1, sm + XS1); }
            CPCOMMIT();
        }

        // ---- bias + relu -> H in reader-order (per-(wh) region) ----
        #pragma unroll
        for (int nt = 0; nt < 4; nt++) {
            int cb = 32 * ns + 8 * nt + 2 * t4;
            float2 bb = *reinterpret_cast<const float2*>(&sm[B1S + cb]);
            int hb = hwr + (4 * ns + nt) * 128;
            uint2 s0, s1;
            s0.x = to_tf32(fmaxf(acc1[nt][0] + bb.x, 0.0f));   // (hi=0, b=0)
            s0.y = to_tf32(fmaxf(acc1[nt][2] + bb.x, 0.0f));   // (hi=1, b=0)
            s1.x = to_tf32(fmaxf(acc1[nt][1] + bb.y, 0.0f));   // (hi=0, b=1)
            s1.y = to_tf32(fmaxf(acc1[nt][3] + bb.y, 0.0f));   // (hi=1, b=1)
            *reinterpret_cast<uint2*>(&smu[hb])     = s0;
            *reinterpret_cast<uint2*>(&smu[hb + 4]) = s1;
        }
        __syncthreads();

        // ======== GEMM2 + fused epilogue (this warp: cc = 2ns, 2ns+1) ========
        const float* eT = eps + base;
        float* oT = out + base;
        const int r0 = 16 * wh + g;

        #pragma unroll
        for (int ccl = 0; ccl < 2; ccl++) {
            const int cc = 2 * ns + ccl;
            const int colb = 64 * cc + 2 * t4;

            // prefetch x/eps for nt 0..3 (hidden under the MMA loop below)
            float2 xa[4][2], ea[4][2];
            #pragma unroll
            for (int nt = 0; nt < 4; nt++) {
                #pragma unroll
                for (int hi = 0; hi < 2; hi++) {
                    int gi = (r0 + 8 * hi) * SDIM + colb + 8 * nt;
                    xa[nt][hi] = *reinterpret_cast<const float2*>(&xT[gi]);
                    ea[nt][hi] = *reinterpret_cast<const float2*>(&eT[gi]);
                }
            }

            float acc2[8][4];
            #pragma unroll
            for (int nt = 0; nt < 8; nt++)
                acc2[nt][0] = acc2[nt][1] = acc2[nt][2] = acc2[nt][3] = 0.0f;

            #pragma unroll
            for (int ks = 0; ks < 8; ks++) {
                uint4 A = *reinterpret_cast<const uint4*>(&smu[hrd + ks * 128]);
                int wr = (8 * ks + t4) * 256 + g * 4;
                uint4 B00 = *reinterpret_cast<const uint4*>(&smu[W2F + wr + (2 * cc) * 32]);
                uint4 B01 = *reinterpret_cast<const uint4*>(&smu[W2F + wr + (2 * cc + 1) * 32]);
                uint4 B10 = *reinterpret_cast<const uint4*>(&smu[W2F + wr + 1024 + (2 * cc) * 32]);
                uint4 B11 = *reinterpret_cast<const uint4*>(&smu[W2F + wr + 1024 + (2 * cc + 1) * 32]);
                mma8(acc2[0], A.x, A.y, A.z, A.w, B00.x, B10.x);
                mma8(acc2[1], A.x, A.y, A.z, A.w, B00.y, B10.y);
                mma8(acc2[2], A.x, A.y, A.z, A.w, B00.z, B10.z);
                mma8(acc2[3], A.x, A.y, A.z, A.w, B00.w, B10.w);
                mma8(acc2[4], A.x, A.y, A.z, A.w, B01.x, B11.x);
                mma8(acc2[5], A.x, A.y, A.z, A.w, B01.y, B11.y);
                mma8(acc2[6], A.x, A.y, A.z, A.w, B01.z, B11.z);
                mma8(acc2[7], A.x, A.y, A.z, A.w, B01.w, B11.w);
            }

            // issue x/eps loads for nt 4..7 (hidden under nt 0..3 math)
            float2 xb[4][2], eb[4][2];
            #pragma unroll
            for (int nt = 0; nt < 4; nt++) {
                #pragma unroll
                for (int hi = 0; hi < 2; hi++) {
                    int gi = (r0 + 8 * hi) * SDIM + colb + 8 * (nt + 4);
                    xb[nt][hi] = *reinterpret_cast<const float2*>(&xT[gi]);
                    eb[nt][hi] = *reinterpret_cast<const float2*>(&eT[gi]);
                }
            }

            // epilogue: out = x + exp2(0.72134752*(d + b2)) * eps
            #pragma unroll
            for (int half = 0; half < 2; half++) {
                #pragma unroll
                for (int nt = 0; nt < 4; nt++) {
                    int ntg = nt + 4 * half;
                    int col = colb + 8 * ntg;
                    float2 bb = *reinterpret_cast<const float2*>(&sm[B2S + col]);
                    float2 (*xv)[2] = half ? xb : xa;
                    float2 (*ev)[2] = half ? eb : ea;
                    #pragma unroll
                    for (int hi = 0; hi < 2; hi++) {
                        int gi = (r0 + 8 * hi) * SDIM + col;
                        float s0 = ex2f((acc2[ntg][2 * hi]     + bb.x) * 0.72134752044f);
                        float s1 = ex2f((acc2[ntg][2 * hi + 1] + bb.y) * 0.72134752044f);
                        float2 o;
                        o.x = fmaf(s0, ev[nt][hi].x, xv[nt][hi].x);
                        o.y = fmaf(s1, ev[nt][hi].y, xv[nt][hi].y);
                        *reinterpret_cast<float2*>(&oT[gi]) = o;
                    }
                }
            }
        }
        __syncthreads();   // H + X slots safe for next tile
    }
}

extern "C" void kernel_launch(void* const* d_in, const int* in_sizes, int n_in,
                              void* d_out, int out_size) {
    const float* x   = (const float*)d_in[0];
    const float* eps = (const float*)d_in[1];
    const float* W1  = (const float*)d_in[2];
    const float* b1  = (const float*)d_in[3];
    const float* W2  = (const float*)d_in[4];
    const float* b2  = (const float*)d_in[5];
    float* out = (float*)d_out;

    int B = in_sizes[0] / SDIM;
    int numTiles = B / TMR;   // 1024

    static int sms = 0;
    if (!sms) {
        cudaDeviceGetAttribute(&sms, cudaDevAttrMultiProcessorCount, 0);
        cudaFuncSetAttribute(mvn_fm_kernel,
                             cudaFuncAttributeMaxDynamicSharedMemorySize, SMEM_BYTES);
    }
    int grid = sms < numTiles ? sms : numTiles;

    mvn_fm_kernel<<<grid, NTHREADS, SMEM_BYTES>>>(x, eps, W1, b1, W2, b2, out, numTiles);
}

// round 10
// speedup vs baseline: 1.8514x; 1.8514x over previous
#include <cuda_runtime.h>
#include <cstdint>

// out = x + exp(0.5*(relu(x@W1+b1)@W2 + b2)) * eps
// Persistent mma.sync tf32 kernel, 512 threads, R5 layouts +
// per-warp eps cp.async pipeline (fixed protocol) + register-resident H frags.

#define SDIM 256
#define TMR  128
#define NTHREADS 512

// smem float-index offsets
#define W1F 0          // W1 tf32 [k=256][64] XOR-swizzled   (64 KB)
#define W2F 16384      // W2 tf32 [k=64][256] XOR-swizzled   (64 KB)
#define XSF 32768      // X ring: 2 slots x (128 rows x 32k) (32 KB)
#define HSF 40960      // H tf32: 128 x 64, swizzled         (32 KB)
#define EPF 49152      // eps: 16 warps x 2 bufs x 256 fl    (32 KB)
#define B1S 57344      // 64 f32
#define B2S 57408      // 256 f32
#define SMEM_FLOATS 57664
#define SMEM_BYTES  (SMEM_FLOATS * 4)   // 230656

__device__ __forceinline__ uint32_t to_tf32(float f) {
    uint32_t r; asm("cvt.rna.tf32.f32 %0, %1;" : "=r"(r) : "f"(f)); return r;
}
__device__ __forceinline__ float ex2f(float f) {
    float r; asm("ex2.approx.f32 %0, %1;" : "=f"(r) : "f"(f)); return r;
}
__device__ __forceinline__ void mma8(float* c,
    uint32_t a0, uint32_t a1, uint32_t a2, uint32_t a3, uint32_t b0, uint32_t b1) {
    asm volatile(
        "mma.sync.aligned.m16n8k8.row.col.f32.tf32.tf32.f32 "
        "{%0,%1,%2,%3},{%4,%5,%6,%7},{%8,%9},{%0,%1,%2,%3};"
        : "+f"(c[0]), "+f"(c[1]), "+f"(c[2]), "+f"(c[3])
        : "r"(a0), "r"(a1), "r"(a2), "r"(a3), "r"(b0), "r"(b1));
}
static __device__ __forceinline__ uint32_t smem_u32(const void* p) {
    uint32_t a;
    asm("{ .reg .u64 t; cvta.to.shared.u64 t, %1; cvt.u32.u64 %0, t; }" : "=r"(a) : "l"(p));
    return a;
}
#define CPA16(s, g)  asm volatile("cp.async.cg.shared.global [%0], [%1], 16;" :: "r"(s), "l"(g))
#define CPCOMMIT()   asm volatile("cp.async.commit_group;" ::: "memory")
#define CPWAIT1()    asm volatile("cp.async.wait_group 1;" ::: "memory")

// block-cooperative load of one X chunk (128 rows x 32 floats) into a slot
static __device__ __forceinline__ void load_chunkX(
    const float* __restrict__ gsrc, float* slot) {
    const int tid = threadIdx.x;
    #pragma unroll
    for (int p = 0; p < 2; p++) {
        int f = tid + NTHREADS * p;         // float4 index, 1024 total
        int m = f >> 3, c4 = f & 7;
        uint32_t dst = smem_u32(slot + m * 32 + 4 * (c4 ^ (m & 7)));
        CPA16(dst, gsrc + m * SDIM + 4 * c4);
    }
}

// per-warp load of one eps chunk (16 rows x 16 cols) into its private buffer
static __device__ __forceinline__ void load_eps(
    const float* __restrict__ eT, int jn, int wh, int ns, int lane, float* ebuf) {
    #pragma unroll
    for (int p = 0; p < 2; p++) {
        int f = lane + 32 * p;              // 0..63 float4s
        int rr = f >> 2, u = f & 3;
        uint32_t dst = smem_u32(ebuf + rr * 16 + 4 * (u ^ (rr & 3)));
        CPA16(dst, eT + (16 * wh + rr) * SDIM + 128 * ns + 16 * jn + 4 * u);
    }
}

__global__ void __launch_bounds__(NTHREADS, 1) mvn_ep_kernel(
    const float* __restrict__ x, const float* __restrict__ eps,
    const float* __restrict__ W1, const float* __restrict__ b1,
    const float* __restrict__ W2, const float* __restrict__ b2,
    float* __restrict__ out, int numTiles)
{
    extern __shared__ float sm[];
    uint32_t* smu = reinterpret_cast<uint32_t*>(sm);

    const int tid  = threadIdx.x;
    const int w    = tid >> 5;
    const int wh   = w & 7;       // row group: rows 16*wh .. +15
    const int ns   = w >> 3;      // column half: 0 or 1
    const int lane = tid & 31;
    const int g    = lane >> 2;
    const int t4   = lane & 3;

    // ---- stage weights (tf32, XOR-swizzled) + biases ----
    #pragma unroll 4
    for (int j = 0; j < 32; j++) {
        int idx = tid + NTHREADS * j;
        int kk = idx >> 6, n = idx & 63;
        smu[W1F + kk * 64 + (n ^ (8 * (kk & 3)))] = to_tf32(W1[idx]);
    }
    #pragma unroll 4
    for (int j = 0; j < 32; j++) {
        int idx = tid + NTHREADS * j;
        int kk = idx >> 8, n = idx & 255;
        smu[W2F + kk * 256 + (n ^ (8 * (kk & 3)))] = to_tf32(W2[idx]);
    }
    if (tid < 64) sm[B1S + tid] = b1[tid];
    if (tid >= 64 && tid < 320) sm[B2S + tid - 64] = b2[tid - 64];
    __syncthreads();

    const int G = gridDim.x;
    const long long TS = (long long)TMR * SDIM;
    int t = blockIdx.x;

    float* slot0 = sm + XSF;
    float* slot1 = sm + XSF + 4096;
    float* ebuf0 = sm + EPF + w * 512;
    float* ebuf1 = ebuf0 + 256;
    const uint32_t* Hs = smu + HSF;

    load_chunkX(x + t * TS + 0 * 32, slot0); CPCOMMIT();   // {X0}
    load_chunkX(x + t * TS + 1 * 32, slot1); CPCOMMIT();   // {X1}

    const int arowX = (16 * wh + g) * 32 + t4;   // X A-fragment base (K=32 slots)
    const int arowH = (16 * wh + g) * 64 + t4;   // H A-fragment base

    for (; t < numTiles; t += G) {
        const long long base = t * TS;
        const float* xT = x + base;
        const float* eT = eps + base;
        float* oT = out + base;

        // ======== GEMM1: this warp -> H cols 32*ns..+31 (8 K=32 chunks) ========
        float acc1[4][4];
        #pragma unroll
        for (int nt = 0; nt < 4; nt++)
            acc1[nt][0] = acc1[nt][1] = acc1[nt][2] = acc1[nt][3] = 0.0f;

        #pragma unroll
        for (int c = 0; c < 8; c++) {
            CPWAIT1();
            __syncthreads();
            const float* xs = (c & 1) ? slot1 : slot0;

            #pragma unroll
            for (int ks = 0; ks < 4; ks++) {
                int a0i = arowX + 4 * ((2 * ks) ^ g);
                uint32_t A0 = to_tf32(xs[a0i]);
                uint32_t A1 = to_tf32(xs[a0i + 256]);
                uint32_t A2 = to_tf32(xs[a0i ^ 4]);
                uint32_t A3 = to_tf32(xs[(a0i ^ 4) + 256]);
                const uint32_t* bp = smu + W1F + (32 * c + 8 * ks + t4) * 64 + 32 * ns + g;
                #pragma unroll
                for (int nt = 0; nt < 4; nt++) {
                    int o = 8 * (nt ^ t4);
                    mma8(acc1[nt], A0, A1, A2, A3, bp[o], bp[o + 256]);
                }
            }
            __syncthreads();

            float* slot = (c & 1) ? slot1 : slot0;
            if (c < 6) {
                load_chunkX(xT + (c + 2) * 32, slot);
            } else {
                int tn = t + G;
                if (tn < numTiles) load_chunkX(x + tn * TS + (c - 6) * 32, slot);
                // bundle eps chunks 0/1 for THIS tile's epilogue
                load_eps(eT, c - 6, wh, ns, lane, (c == 6) ? ebuf0 : ebuf1);
            }
            CPCOMMIT();
        }

        // ---- bias + relu -> H (tf32, swizzled) ----
        {
            const int m0 = (16 * wh + g) * 64;
            #pragma unroll
            for (int nt = 0; nt < 4; nt++) {
                int col = 32 * ns + 8 * nt + 2 * t4;
                float2 bb = *reinterpret_cast<const float2*>(&sm[B1S + col]);
                uint2 p0, p1;
                p0.x = to_tf32(fmaxf(acc1[nt][0] + bb.x, 0.0f));
                p0.y = to_tf32(fmaxf(acc1[nt][1] + bb.y, 0.0f));
                p1.x = to_tf32(fmaxf(acc1[nt][2] + bb.x, 0.0f));
                p1.y = to_tf32(fmaxf(acc1[nt][3] + bb.y, 0.0f));
                int hi = m0 + 4 * ((col >> 2) ^ g) + (col & 3);
                *reinterpret_cast<uint2*>(&smu[HSF + hi])       = p0;
                *reinterpret_cast<uint2*>(&smu[HSF + hi + 512]) = p1;
            }
        }
        __syncthreads();

        // ---- preload ALL H A-fragments into registers (32 regs) ----
        uint4 hA[8];
        #pragma unroll
        for (int ks = 0; ks < 8; ks++) {
            int a0i = arowH + 4 * ((2 * ks) ^ g);
            hA[ks].x = Hs[a0i];
            hA[ks].y = Hs[a0i + 512];
            hA[ks].z = Hs[a0i ^ 4];
            hA[ks].w = Hs[(a0i ^ 4) + 512];
        }

        // ======== GEMM2 + epilogue: 8 chunks of 16 cols (this warp's half) ========
        #pragma unroll
        for (int j = 0; j < 8; j++) {
            // x loads first (independent of cp.async state; hide under MMAs)
            float2 xv[2][2];
            #pragma unroll
            for (int nt = 0; nt < 2; nt++)
                #pragma unroll
                for (int hi = 0; hi < 2; hi++) {
                    int col = 128 * ns + 16 * j + 8 * nt + 2 * t4;
                    int row = 16 * wh + g + 8 * hi;
                    xv[nt][hi] = *reinterpret_cast<const float2*>(&xT[row * SDIM + col]);
                }

            CPWAIT1();      // eps chunk j's group complete (committed 2 steps back)
            __syncwarp();
            const float* eb = (j & 1) ? ebuf1 : ebuf0;

            float acc2[2][4];
            acc2[0][0] = acc2[0][1] = acc2[0][2] = acc2[0][3] = 0.0f;
            acc2[1][0] = acc2[1][1] = acc2[1][2] = acc2[1][3] = 0.0f;

            const int nc0 = 128 * ns + 16 * j + g;
            #pragma unroll
            for (int ks = 0; ks < 8; ks++) {
                const uint32_t* bp = smu + W2F + (8 * ks + t4) * 256;
                uint32_t b00 = bp[nc0 ^ (8 * t4)];
                uint32_t b01 = bp[(nc0 + 8) ^ (8 * t4)];
                uint32_t b10 = bp[1024 + (nc0 ^ (8 * t4))];
                uint32_t b11 = bp[1024 + ((nc0 + 8) ^ (8 * t4))];
                mma8(acc2[0], hA[ks].x, hA[ks].y, hA[ks].z, hA[ks].w, b00, b10);
                mma8(acc2[1], hA[ks].x, hA[ks].y, hA[ks].z, hA[ks].w, b01, b11);
            }

            // eps reads (LDS from this chunk's buffer)
            float2 ev[2][2];
            #pragma unroll
            for (int nt = 0; nt < 2; nt++)
                #pragma unroll
                for (int hi = 0; hi < 2; hi++) {
                    int rr = g + 8 * hi;
                    int u  = (2 * nt + (t4 >> 1)) ^ (rr & 3);
                    ev[nt][hi] = *reinterpret_cast<const float2*>(
                        &eb[rr * 16 + 4 * u + 2 * (t4 & 1)]);
                }

            // math + stores: out = x + exp2(0.72134752*(d + b2)) * eps
            #pragma unroll
            for (int nt = 0; nt < 2; nt++) {
                int col = 128 * ns + 16 * j + 8 * nt + 2 * t4;
                float2 bb = *reinterpret_cast<const float2*>(&sm[B2S + col]);
                #pragma unroll
                for (int hi = 0; hi < 2; hi++) {
                    int row = 16 * wh + g + 8 * hi;
                    float s0 = ex2f((acc2[nt][2 * hi]     + bb.x) * 0.72134752044f);
                    float s1 = ex2f((acc2[nt][2 * hi + 1] + bb.y) * 0.72134752044f);
                    float2 o;
                    o.x = fmaf(s0, ev[nt][hi].x, xv[nt][hi].x);
                    o.y = fmaf(s1, ev[nt][hi].y, xv[nt][hi].y);
                    *reinterpret_cast<float2*>(&oT[row * SDIM + col]) = o;
                }
            }

            // all lanes done reading chunk j's buffer, then refill with j+2
            __syncwarp();
            if (j < 6) load_eps(eT, j + 2, wh, ns, lane, (j & 1) ? ebuf1 : ebuf0);
            CPCOMMIT();   // one group per step (empty at j=6,7) keeps alignment
        }
        // next tile's GEMM1 barriers provide X-slot ordering
    }
}

extern "C" void kernel_launch(void* const* d_in, const int* in_sizes, int n_in,
                              void* d_out, int out_size) {
    const float* x   = (const float*)d_in[0];
    const float* eps = (const float*)d_in[1];
    const float* W1  = (const float*)d_in[2];
    const float* b1  = (const float*)d_in[3];
    const float* W2  = (const float*)d_in[4];
    const float* b2  = (const float*)d_in[5];
    float* out = (float*)d_out;

    int B = in_sizes[0] / SDIM;
    int numTiles = B / TMR;   // 1024

    static int sms = 0;
    if (!sms) {
        cudaDeviceGetAttribute(&sms, cudaDevAttrMultiProcessorCount, 0);
        cudaFuncSetAttribute(mvn_ep_kernel,
                             cudaFuncAttributeMaxDynamicSharedMemorySize, SMEM_BYTES);
    }
    int grid = sms < numTiles ? sms : numTiles;

    mvn_ep_kernel<<<grid, NTHREADS, SMEM_BYTES>>>(x, eps, W1, b1, W2, b2, out, numTiles);
}